// round 7
// baseline (speedup 1.0000x reference)
#include <cuda_runtime.h>

// Shapes: (64, 4, 256, 256) f32.
#define B 64
#define PER_BATCH (4 * 256 * 256)   // 262144
#define MARGIN 1.0f
#define NUM_PAIRS (B * (B - 1) / 2) // 2016

#define THREADS 256
#define VEC_PER_THREAD 2                                  // float4s per thread per tensor
#define ELEMS_PER_BLOCK (THREADS * VEC_PER_THREAD * 4)    // 2048
#define CHUNKS_PER_BATCH (PER_BATCH / ELEMS_PER_BLOCK)    // 128
#define GRID (B * CHUNKS_PER_BATCH)                       // 8192

// Device-global scratch (zero-initialized at module load; self-reset by the
// finalizing block at the end of every launch, so graph replays start clean).
__device__ float        g_err[B];
__device__ float        g_unc[B];
__device__ unsigned int g_arrived;

__global__ __launch_bounds__(THREADS, 8)   // cap regs -> 8 blocks/SM
void fused_kernel(const float* __restrict__ pm,
                  const float* __restrict__ ps,
                  const float* __restrict__ tg,
                  float* __restrict__ out) {
    int batch = blockIdx.x / CHUNKS_PER_BATCH;
    int chunk = blockIdx.x % CHUNKS_PER_BATCH;
    size_t base = (size_t)batch * PER_BATCH + (size_t)chunk * ELEMS_PER_BLOCK;

    const float4* pm4 = (const float4*)(pm + base);
    const float4* ps4 = (const float4*)(ps + base);
    const float4* tg4 = (const float4*)(tg + base);

    float e_sum = 0.0f, u_sum = 0.0f;

    #pragma unroll
    for (int i = 0; i < VEC_PER_THREAD; i++) {
        int idx = threadIdx.x + i * THREADS;   // coalesced
        float4 a = pm4[idx];
        float4 t = tg4[idx];
        float4 s = ps4[idx];
        e_sum += fabsf(a.x - t.x) + fabsf(a.y - t.y)
               + fabsf(a.z - t.z) + fabsf(a.w - t.w);
        u_sum += s.x + s.y + s.z + s.w;
    }

    // warp reduce
    #pragma unroll
    for (int off = 16; off > 0; off >>= 1) {
        e_sum += __shfl_down_sync(0xFFFFFFFFu, e_sum, off);
        u_sum += __shfl_down_sync(0xFFFFFFFFu, u_sum, off);
    }

    __shared__ float se[THREADS / 32], su[THREADS / 32];
    int lane = threadIdx.x & 31;
    int wid  = threadIdx.x >> 5;
    if (lane == 0) { se[wid] = e_sum; su[wid] = u_sum; }
    __syncthreads();

    if (wid == 0) {
        e_sum = (lane < THREADS / 32) ? se[lane] : 0.0f;
        u_sum = (lane < THREADS / 32) ? su[lane] : 0.0f;
        #pragma unroll
        for (int off = 4; off > 0; off >>= 1) {
            e_sum += __shfl_down_sync(0xFFFFFFFFu, e_sum, off);
            u_sum += __shfl_down_sync(0xFFFFFFFFu, u_sum, off);
        }
        if (lane == 0) {
            atomicAdd(&g_err[batch], e_sum);
            atomicAdd(&g_unc[batch], u_sum);
        }
    }

    // ── last-block-arrival finalize ─────────────────────────────────────
    __shared__ unsigned int s_is_last;
    __syncthreads();                 // this block's atomics have been issued
    if (threadIdx.x == 0) {
        __threadfence();             // make this block's adds globally visible
        unsigned int n = atomicAdd(&g_arrived, 1u);
        s_is_last = (n == GRID - 1u) ? 1u : 0u;
    }
    __syncthreads();
    if (s_is_last == 0u) return;

    __threadfence();                 // order counter observation before accumulator reads

    __shared__ float err_s[B], unc_s[B];
    int i = threadIdx.x;
    if (i < B) {
        const float inv_n = 1.0f / (float)PER_BATCH;
        // __ldcg: read at L2 (coherent with global atomics), bypass L1
        err_s[i] = __ldcg(&g_err[i]) * inv_n;
        unc_s[i] = __ldcg(&g_unc[i]) * inv_n;
    }
    __syncthreads();

    if (i < B) {
        float ei = err_s[i], ui = unc_s[i];
        float sum = 0.0f;
        #pragma unroll 4
        for (int j = i + 1; j < B; j++) {
            float ej = err_s[j], uj = unc_s[j];
            float d = (ei > ej) ? (uj - ui) : (ui - uj);
            sum += fmaxf(d + MARGIN, 0.0f);
        }
        #pragma unroll
        for (int off = 16; off > 0; off >>= 1)
            sum += __shfl_down_sync(0xFFFFFFFFu, sum, off);

        __shared__ float ws[2];
        if ((i & 31) == 0) ws[i >> 5] = sum;
        __syncthreads();
        if (i == 0) out[0] = (ws[0] + ws[1]) / (float)NUM_PAIRS;

        // reset scratch for the next graph replay (L2 write-through so the next
        // launch's __ldcg reads can never observe a stale cached line)
        __stcg(&g_err[i], 0.0f);
        __stcg(&g_unc[i], 0.0f);
        if (i == 0) { __threadfence(); g_arrived = 0u; }
    }
}

extern "C" void kernel_launch(void* const* d_in, const int* in_sizes, int n_in,
                              void* d_out, int out_size) {
    const float* pred_mean = (const float*)d_in[0];
    const float* pred_std  = (const float*)d_in[1];
    const float* targets   = (const float*)d_in[2];
    fused_kernel<<<GRID, THREADS>>>(pred_mean, pred_std, targets, (float*)d_out);
}

// round 8
// speedup vs baseline: 1.0977x; 1.0977x over previous
#include <cuda_runtime.h>

// Shapes: (64, 4, 256, 256) f32.
#define B 64
#define PER_BATCH (4 * 256 * 256)   // 262144
#define MARGIN 1.0f
#define NUM_PAIRS (B * (B - 1) / 2) // 2016

#define THREADS 256
// Each thread: 2 x 256-bit loads per tensor = 16 floats.
#define V8_PER_THREAD 2
#define ELEMS_PER_BLOCK (THREADS * V8_PER_THREAD * 8)     // 4096 (same as R4)
#define CHUNKS_PER_BATCH (PER_BATCH / ELEMS_PER_BLOCK)    // 64
#define GRID (B * CHUNKS_PER_BATCH)                       // 4096

// Device-global scratch (zero-initialized at module load; self-reset by the
// finalizing block at the end of every launch, so graph replays start clean).
__device__ float        g_err[B];
__device__ float        g_unc[B];
__device__ unsigned int g_arrived;

// 256-bit non-coherent global load (sm_100a+). Falls back to 2x float4.
__device__ __forceinline__ void ldg_nc_v8(const float* __restrict__ p,
                                          float4& a, float4& b) {
#if defined(__CUDA_ARCH__) && (__CUDA_ARCH__ >= 1000)
    asm volatile("ld.global.nc.v8.f32 {%0,%1,%2,%3,%4,%5,%6,%7}, [%8];"
                 : "=f"(a.x), "=f"(a.y), "=f"(a.z), "=f"(a.w),
                   "=f"(b.x), "=f"(b.y), "=f"(b.z), "=f"(b.w)
                 : "l"(p));
#else
    a = __ldg((const float4*)p);
    b = __ldg((const float4*)p + 1);
#endif
}

__global__ __launch_bounds__(THREADS)
void fused_kernel(const float* __restrict__ pm,
                  const float* __restrict__ ps,
                  const float* __restrict__ tg,
                  float* __restrict__ out) {
    int batch = blockIdx.x / CHUNKS_PER_BATCH;
    int chunk = blockIdx.x % CHUNKS_PER_BATCH;
    size_t base = (size_t)batch * PER_BATCH + (size_t)chunk * ELEMS_PER_BLOCK;

    const float* pmb = pm + base;
    const float* psb = ps + base;
    const float* tgb = tg + base;

    float e0 = 0.0f, e1 = 0.0f, u0 = 0.0f, u1 = 0.0f;  // split chains

    #pragma unroll
    for (int i = 0; i < V8_PER_THREAD; i++) {
        // thread t, iter i reads bytes [ (i*THREADS + t) * 32 , +32 )  — warp
        // covers 1024 contiguous bytes per load instruction.
        size_t off = ((size_t)i * THREADS + threadIdx.x) * 8;
        float4 a0, a1, t0, t1, s0, s1;
        ldg_nc_v8(pmb + off, a0, a1);
        ldg_nc_v8(tgb + off, t0, t1);
        ldg_nc_v8(psb + off, s0, s1);
        e0 += fabsf(a0.x - t0.x) + fabsf(a0.y - t0.y)
            + fabsf(a0.z - t0.z) + fabsf(a0.w - t0.w);
        e1 += fabsf(a1.x - t1.x) + fabsf(a1.y - t1.y)
            + fabsf(a1.z - t1.z) + fabsf(a1.w - t1.w);
        u0 += s0.x + s0.y + s0.z + s0.w;
        u1 += s1.x + s1.y + s1.z + s1.w;
    }
    float e_sum = e0 + e1;
    float u_sum = u0 + u1;

    // warp reduce
    #pragma unroll
    for (int off = 16; off > 0; off >>= 1) {
        e_sum += __shfl_down_sync(0xFFFFFFFFu, e_sum, off);
        u_sum += __shfl_down_sync(0xFFFFFFFFu, u_sum, off);
    }

    __shared__ float se[THREADS / 32], su[THREADS / 32];
    int lane = threadIdx.x & 31;
    int wid  = threadIdx.x >> 5;
    if (lane == 0) { se[wid] = e_sum; su[wid] = u_sum; }
    __syncthreads();

    if (wid == 0) {
        e_sum = (lane < THREADS / 32) ? se[lane] : 0.0f;
        u_sum = (lane < THREADS / 32) ? su[lane] : 0.0f;
        #pragma unroll
        for (int off = 4; off > 0; off >>= 1) {
            e_sum += __shfl_down_sync(0xFFFFFFFFu, e_sum, off);
            u_sum += __shfl_down_sync(0xFFFFFFFFu, u_sum, off);
        }
        if (lane == 0) {
            atomicAdd(&g_err[batch], e_sum);
            atomicAdd(&g_unc[batch], u_sum);
        }
    }

    // ── last-block-arrival finalize ─────────────────────────────────────
    __shared__ unsigned int s_is_last;
    __syncthreads();                 // this block's atomics have been issued
    if (threadIdx.x == 0) {
        __threadfence();             // make this block's adds globally visible
        unsigned int n = atomicAdd(&g_arrived, 1u);
        s_is_last = (n == GRID - 1u) ? 1u : 0u;
    }
    __syncthreads();
    if (s_is_last == 0u) return;

    __threadfence();                 // order counter observation before accumulator reads

    __shared__ float err_s[B], unc_s[B];
    int i = threadIdx.x;
    if (i < B) {
        const float inv_n = 1.0f / (float)PER_BATCH;
        // __ldcg: read at L2 (coherent with global atomics), bypass L1
        err_s[i] = __ldcg(&g_err[i]) * inv_n;
        unc_s[i] = __ldcg(&g_unc[i]) * inv_n;
    }
    __syncthreads();

    if (i < B) {
        float ei = err_s[i], ui = unc_s[i];
        float sum = 0.0f;
        #pragma unroll 4
        for (int j = i + 1; j < B; j++) {
            float ej = err_s[j], uj = unc_s[j];
            float d = (ei > ej) ? (uj - ui) : (ui - uj);
            sum += fmaxf(d + MARGIN, 0.0f);
        }
        #pragma unroll
        for (int off = 16; off > 0; off >>= 1)
            sum += __shfl_down_sync(0xFFFFFFFFu, sum, off);

        __shared__ float ws[2];
        if ((i & 31) == 0) ws[i >> 5] = sum;
        __syncthreads();
        if (i == 0) out[0] = (ws[0] + ws[1]) / (float)NUM_PAIRS;

        // reset scratch for the next graph replay (L2 write-through so the next
        // launch's __ldcg reads can never observe a stale cached line)
        __stcg(&g_err[i], 0.0f);
        __stcg(&g_unc[i], 0.0f);
        if (i == 0) { __threadfence(); g_arrived = 0u; }
    }
}

extern "C" void kernel_launch(void* const* d_in, const int* in_sizes, int n_in,
                              void* d_out, int out_size) {
    const float* pred_mean = (const float*)d_in[0];
    const float* pred_std  = (const float*)d_in[1];
    const float* targets   = (const float*)d_in[2];
    fused_kernel<<<GRID, THREADS>>>(pred_mean, pred_std, targets, (float*)d_out);
}

// round 13
// speedup vs baseline: 1.1120x; 1.0130x over previous
#include <cuda_runtime.h>

// Shapes: (64, 4, 256, 256) f32.
#define B 64
#define PER_BATCH (4 * 256 * 256)   // 262144
#define MARGIN 1.0f
#define NUM_PAIRS (B * (B - 1) / 2) // 2016

#define THREADS 256
#define VEC_PER_THREAD 4                                  // float4s per thread per tensor
#define ELEMS_PER_BLOCK (THREADS * VEC_PER_THREAD * 4)    // 4096
#define CHUNKS_PER_BATCH (PER_BATCH / ELEMS_PER_BLOCK)    // 64
#define GRID (B * CHUNKS_PER_BATCH)                       // 4096

// Device-global scratch (zero-initialized at module load; self-reset by the
// finalizing block at the end of every launch, so graph replays start clean).
__device__ float        g_err[B];
__device__ float        g_unc[B];
__device__ unsigned int g_arrived;

__global__ __launch_bounds__(THREADS)
void fused_kernel(const float* __restrict__ pm,
                  const float* __restrict__ ps,
                  const float* __restrict__ tg,
                  float* __restrict__ out) {
    int batch = blockIdx.x / CHUNKS_PER_BATCH;
    int chunk = blockIdx.x % CHUNKS_PER_BATCH;
    size_t base = (size_t)batch * PER_BATCH + (size_t)chunk * ELEMS_PER_BLOCK;

    const float4* pm4 = (const float4*)(pm + base);
    const float4* ps4 = (const float4*)(ps + base);
    const float4* tg4 = (const float4*)(tg + base);

    float e_sum = 0.0f, u_sum = 0.0f;

    #pragma unroll
    for (int i = 0; i < VEC_PER_THREAD; i++) {
        int idx = threadIdx.x + i * THREADS;   // coalesced
        float4 a = __ldcs(&pm4[idx]);          // evict-first: read-once streams
        float4 t = __ldcs(&tg4[idx]);
        float4 s = __ldcs(&ps4[idx]);
        e_sum += fabsf(a.x - t.x) + fabsf(a.y - t.y)
               + fabsf(a.z - t.z) + fabsf(a.w - t.w);
        u_sum += s.x + s.y + s.z + s.w;
    }

    // warp reduce
    #pragma unroll
    for (int off = 16; off > 0; off >>= 1) {
        e_sum += __shfl_down_sync(0xFFFFFFFFu, e_sum, off);
        u_sum += __shfl_down_sync(0xFFFFFFFFu, u_sum, off);
    }

    __shared__ float se[THREADS / 32], su[THREADS / 32];
    int lane = threadIdx.x & 31;
    int wid  = threadIdx.x >> 5;
    if (lane == 0) { se[wid] = e_sum; su[wid] = u_sum; }
    __syncthreads();

    if (wid == 0) {
        e_sum = (lane < THREADS / 32) ? se[lane] : 0.0f;
        u_sum = (lane < THREADS / 32) ? su[lane] : 0.0f;
        #pragma unroll
        for (int off = 4; off > 0; off >>= 1) {
            e_sum += __shfl_down_sync(0xFFFFFFFFu, e_sum, off);
            u_sum += __shfl_down_sync(0xFFFFFFFFu, u_sum, off);
        }
        if (lane == 0) {
            atomicAdd(&g_err[batch], e_sum);
            atomicAdd(&g_unc[batch], u_sum);
        }
    }

    // ── last-block-arrival finalize ─────────────────────────────────────
    __shared__ unsigned int s_is_last;
    __syncthreads();                 // this block's atomics have been issued
    if (threadIdx.x == 0) {
        __threadfence();             // make this block's adds globally visible
        unsigned int n = atomicAdd(&g_arrived, 1u);
        s_is_last = (n == GRID - 1u) ? 1u : 0u;
    }
    __syncthreads();
    if (s_is_last == 0u) return;

    __threadfence();                 // order counter observation before accumulator reads

    __shared__ float err_s[B], unc_s[B];
    int i = threadIdx.x;
    if (i < B) {
        const float inv_n = 1.0f / (float)PER_BATCH;
        // __ldcg: read at L2 (coherent with global atomics), bypass L1
        err_s[i] = __ldcg(&g_err[i]) * inv_n;
        unc_s[i] = __ldcg(&g_unc[i]) * inv_n;
    }
    __syncthreads();

    if (i < B) {
        float ei = err_s[i], ui = unc_s[i];
        float sum = 0.0f;
        #pragma unroll 4
        for (int j = i + 1; j < B; j++) {
            float ej = err_s[j], uj = unc_s[j];
            float d = (ei > ej) ? (uj - ui) : (ui - uj);
            sum += fmaxf(d + MARGIN, 0.0f);
        }
        #pragma unroll
        for (int off = 16; off > 0; off >>= 1)
            sum += __shfl_down_sync(0xFFFFFFFFu, sum, off);

        __shared__ float ws[2];
        if ((i & 31) == 0) ws[i >> 5] = sum;
        __syncthreads();
        if (i == 0) out[0] = (ws[0] + ws[1]) / (float)NUM_PAIRS;

        // reset scratch for the next graph replay (L2 write-through so the next
        // launch's __ldcg reads can never observe a stale cached line)
        __stcg(&g_err[i], 0.0f);
        __stcg(&g_unc[i], 0.0f);
        if (i == 0) { __threadfence(); g_arrived = 0u; }
    }
}

extern "C" void kernel_launch(void* const* d_in, const int* in_sizes, int n_in,
                              void* d_out, int out_size) {
    const float* pred_mean = (const float*)d_in[0];
    const float* pred_std  = (const float*)d_in[1];
    const float* targets   = (const float*)d_in[2];
    fused_kernel<<<GRID, THREADS>>>(pred_mean, pred_std, targets, (float*)d_out);
}